// round 2
// baseline (speedup 1.0000x reference)
#include <cuda_runtime.h>
#include <math.h>

#define BB 16
#define TT 16
#define LL 128
#define XX 256
#define HH 512
#define YY 256

// ---------------- device scratch (static allocation; no runtime alloc) ----------------
__device__ __align__(16) float g_w1[BB * HH * XX];   // 8 MB
__device__ __align__(16) float g_w2[BB * HH * HH];   // 16 MB
__device__ __align__(16) float g_w3[BB * HH * HH];   // 16 MB
__device__ __align__(16) float g_w4[BB * YY * HH];   // 8 MB
__device__ __align__(16) float g_b1[BB * HH];
__device__ __align__(16) float g_b2[BB * HH];
__device__ __align__(16) float g_b3[BB * HH];

__device__ __align__(16) float g_h1[BB * HH];
__device__ __align__(16) float g_h2[BB * HH];
__device__ __align__(16) float g_h3[BB * HH];
__device__ __align__(16) float g_hg[BB * HH];
__device__ __align__(16) float g_dlogit[BB * YY];
__device__ __align__(16) float g_dz3[BB * HH];
__device__ __align__(16) float g_dz2[BB * HH];

__device__ __align__(16) float g_ea[BB * LL * HH];   // 4 MB eval ping
__device__ __align__(16) float g_eb[BB * LL * HH];   // 4 MB eval pong

// ---------------- helpers ----------------
__device__ __forceinline__ float warp_sum(float v) {
    v += __shfl_xor_sync(0xffffffffu, v, 16);
    v += __shfl_xor_sync(0xffffffffu, v, 8);
    v += __shfl_xor_sync(0xffffffffu, v, 4);
    v += __shfl_xor_sync(0xffffffffu, v, 2);
    v += __shfl_xor_sync(0xffffffffu, v, 1);
    return v;
}

// ---------------- init: broadcast shared params into per-example fast weights ----------
__global__ void k_init(const float* __restrict__ fc1, const float* __restrict__ b1,
                       const float* __restrict__ fc2, const float* __restrict__ b2,
                       const float* __restrict__ fc3, const float* __restrict__ b3,
                       const float* __restrict__ fc4) {
    int stride = gridDim.x * blockDim.x;
    int i0 = blockIdx.x * blockDim.x + threadIdx.x;
    for (int i = i0; i < BB * HH * XX; i += stride) g_w1[i] = fc1[i & (HH * XX - 1)];
    for (int i = i0; i < BB * HH * HH; i += stride) g_w2[i] = fc2[i & (HH * HH - 1)];
    for (int i = i0; i < BB * HH * HH; i += stride) g_w3[i] = fc3[i & (HH * HH - 1)];
    for (int i = i0; i < BB * YY * HH; i += stride) g_w4[i] = fc4[i & (YY * HH - 1)];
    for (int i = i0; i < BB * HH; i += stride) {
        g_b1[i] = b1[i & (HH - 1)];
        g_b2[i] = b2[i & (HH - 1)];
        g_b3[i] = b3[i & (HH - 1)];
    }
}

// ---------------- training forward: one warp per output row -------------------
__global__ void k_fwd1(const float* __restrict__ tx, int t) {
    int gw = (blockIdx.x * blockDim.x + threadIdx.x) >> 5;
    int lane = threadIdx.x & 31;
    int b = gw >> 9, r = gw & 511;
    const float4* w = reinterpret_cast<const float4*>(g_w1 + ((size_t)b * HH + r) * XX);
    const float4* xv = reinterpret_cast<const float4*>(tx + ((size_t)(b * TT + t)) * XX);
    float acc = 0.f;
#pragma unroll
    for (int k = lane, it = 0; it < XX / 128; it++, k += 32) {
        float4 a = w[k], c = xv[k];
        acc += a.x * c.x + a.y * c.y + a.z * c.z + a.w * c.w;
    }
    acc = warp_sum(acc);
    if (lane == 0) {
        float z = acc + g_b1[b * HH + r];
        g_h1[b * HH + r] = fmaxf(z, 0.f);
    }
}

__global__ void k_fwd2() {
    int gw = (blockIdx.x * blockDim.x + threadIdx.x) >> 5;
    int lane = threadIdx.x & 31;
    int b = gw >> 9, r = gw & 511;
    const float4* w = reinterpret_cast<const float4*>(g_w2 + ((size_t)b * HH + r) * HH);
    const float4* xv = reinterpret_cast<const float4*>(g_h1 + (size_t)b * HH);
    float acc = 0.f;
#pragma unroll
    for (int k = lane, it = 0; it < HH / 128; it++, k += 32) {
        float4 a = w[k], c = xv[k];
        acc += a.x * c.x + a.y * c.y + a.z * c.z + a.w * c.w;
    }
    acc = warp_sum(acc);
    if (lane == 0) {
        float z = acc + g_b2[b * HH + r];
        g_h2[b * HH + r] = fmaxf(z, 0.f);
    }
}

__global__ void k_fwd3(const float* __restrict__ tg, int t) {
    int gw = (blockIdx.x * blockDim.x + threadIdx.x) >> 5;
    int lane = threadIdx.x & 31;
    int b = gw >> 9, r = gw & 511;
    const float4* w = reinterpret_cast<const float4*>(g_w3 + ((size_t)b * HH + r) * HH);
    const float4* xv = reinterpret_cast<const float4*>(g_h2 + (size_t)b * HH);
    float acc = 0.f;
#pragma unroll
    for (int k = lane, it = 0; it < HH / 128; it++, k += 32) {
        float4 a = w[k], c = xv[k];
        acc += a.x * c.x + a.y * c.y + a.z * c.z + a.w * c.w;
    }
    acc = warp_sum(acc);
    if (lane == 0) {
        float z = acc + g_b3[b * HH + r];
        float h3 = fmaxf(z, 0.f);
        g_h3[b * HH + r] = h3;
        g_hg[b * HH + r] = h3 * tg[((size_t)(b * TT + t)) * HH + r];
    }
}

__global__ void k_fwd4(const float* __restrict__ ty, int t) {
    int gw = (blockIdx.x * blockDim.x + threadIdx.x) >> 5;
    int lane = threadIdx.x & 31;
    int b = gw >> 8, r = gw & 255;
    const float4* w = reinterpret_cast<const float4*>(g_w4 + ((size_t)b * YY + r) * HH);
    const float4* xv = reinterpret_cast<const float4*>(g_hg + (size_t)b * HH);
    float acc = 0.f;
#pragma unroll
    for (int k = lane, it = 0; it < HH / 128; it++, k += 32) {
        float4 a = w[k], c = xv[k];
        acc += a.x * c.x + a.y * c.y + a.z * c.z + a.w * c.w;
    }
    acc = warp_sum(acc);
    if (lane == 0) {
        float yv = ty[((size_t)(b * TT + t)) * YY + r];
        g_dlogit[b * YY + r] = (2.f / (float)YY) * (acc - yv);
    }
}

// ---------------- backward (transposed matvec + weight update, fused) ---------
// grid: 16 examples * 4 column-chunks of 128; block: 256 threads (i-range split in half)
__global__ void k_bwd4(const float* __restrict__ tg, const float* __restrict__ loglr, int t) {
    int b = blockIdx.x >> 2, jc = blockIdx.x & 3;
    int tid = threadIdx.x;
    int j = (jc << 7) + (tid & 127);
    int half = tid >> 7;
    __shared__ float s_dl[YY];
    __shared__ float s_acc[256];
    for (int i = tid; i < YY; i += 256) s_dl[i] = g_dlogit[b * YY + i];
    __syncthreads();
    float lr = expf(*loglr);
    float hgj = g_hg[b * HH + j];
    float* wp = g_w4 + (size_t)b * (YY * HH) + j;
    float acc = 0.f;
    int i0 = half * (YY / 2);
#pragma unroll 16
    for (int i = i0; i < i0 + YY / 2; i++) {
        float w = wp[(size_t)i * HH];
        float dl = s_dl[i];
        acc = fmaf(w, dl, acc);
        wp[(size_t)i * HH] = fmaf(-lr * dl, hgj, w);
    }
    s_acc[tid] = acc;
    __syncthreads();
    if (half == 0) {
        float dhg = s_acc[tid] + s_acc[tid + 128];
        float gatev = tg[((size_t)(b * TT + t)) * HH + j];
        float h3 = g_h3[b * HH + j];
        float dz3 = (h3 > 0.f) ? dhg * gatev : 0.f;
        g_dz3[b * HH + j] = dz3;
        g_b3[b * HH + j] = g_b3[b * HH + j] - lr * dz3;
    }
}

__global__ void k_bwd3(const float* __restrict__ loglr) {
    int b = blockIdx.x >> 2, jc = blockIdx.x & 3;
    int tid = threadIdx.x;
    int j = (jc << 7) + (tid & 127);
    int half = tid >> 7;
    __shared__ float s_dz[HH];
    __shared__ float s_acc[256];
    for (int i = tid; i < HH; i += 256) s_dz[i] = g_dz3[b * HH + i];
    __syncthreads();
    float lr = expf(*loglr);
    float h2j = g_h2[b * HH + j];
    float* wp = g_w3 + (size_t)b * (HH * HH) + j;
    float acc = 0.f;
    int i0 = half * (HH / 2);
#pragma unroll 16
    for (int i = i0; i < i0 + HH / 2; i++) {
        float w = wp[(size_t)i * HH];
        float dz = s_dz[i];
        acc = fmaf(w, dz, acc);
        wp[(size_t)i * HH] = fmaf(-lr * dz, h2j, w);
    }
    s_acc[tid] = acc;
    __syncthreads();
    if (half == 0) {
        float dh2 = s_acc[tid] + s_acc[tid + 128];
        float dz2 = (h2j > 0.f) ? dh2 : 0.f;
        g_dz2[b * HH + j] = dz2;
        g_b2[b * HH + j] = g_b2[b * HH + j] - lr * dz2;
    }
}

__global__ void k_bwd2(const float* __restrict__ tx, const float* __restrict__ loglr, int t) {
    int b = blockIdx.x >> 2, jc = blockIdx.x & 3;
    int tid = threadIdx.x;
    int j = (jc << 7) + (tid & 127);
    int half = tid >> 7;
    __shared__ float s_dz[HH];
    __shared__ float s_acc[256];
    __shared__ float s_dz1[128];
    __shared__ __align__(16) float s_x[XX];
    for (int i = tid; i < HH; i += 256) s_dz[i] = g_dz2[b * HH + i];
    for (int k = tid; k < XX; k += 256) s_x[k] = tx[((size_t)(b * TT + t)) * XX + k];
    __syncthreads();
    float lr = expf(*loglr);
    float h1j = g_h1[b * HH + j];
    float* wp = g_w2 + (size_t)b * (HH * HH) + j;
    float acc = 0.f;
    int i0 = half * (HH / 2);
#pragma unroll 16
    for (int i = i0; i < i0 + HH / 2; i++) {
        float w = wp[(size_t)i * HH];
        float dz = s_dz[i];
        acc = fmaf(w, dz, acc);
        wp[(size_t)i * HH] = fmaf(-lr * dz, h1j, w);
    }
    s_acc[tid] = acc;
    __syncthreads();
    if (half == 0) {
        float dh1 = s_acc[tid] + s_acc[tid + 128];
        float dz1 = (h1j > 0.f) ? dh1 : 0.f;
        g_b1[b * HH + j] = g_b1[b * HH + j] - lr * dz1;
        s_dz1[tid] = dz1;  // tid < 128 here
    }
    __syncthreads();
    // fc1 slab update for hidden rows [jc*128, jc*128+128)
    float4* w1 = reinterpret_cast<float4*>(g_w1 + ((size_t)b * HH + (jc << 7)) * XX);
    const float4* sx4 = reinterpret_cast<const float4*>(s_x);
#pragma unroll 8
    for (int e = tid; e < 128 * (XX / 4); e += 256) {
        int r = e >> 6;
        int k4 = e & 63;
        float c = lr * s_dz1[r];
        float4 w = w1[e];
        float4 xv = sx4[k4];
        w.x -= c * xv.x; w.y -= c * xv.y; w.z -= c * xv.z; w.w -= c * xv.w;
        w1[e] = w;
    }
}

// ---------------- eval: tiled fp32 GEMM per layer ------------------------------
// block: 256 threads computing [128 n x 64 l] per (b, nb, lb) tile.
template <int LAYER>
__global__ void __launch_bounds__(256) k_eval(const float* __restrict__ extin,
                                              const float* __restrict__ gate,
                                              float* __restrict__ outp) {
    constexpr int N = (LAYER == 4) ? YY : HH;
    constexpr int K = (LAYER == 1) ? XX : HH;
    constexpr int NBLK = N / 128;

    __shared__ float Ws[32 * 129];
    __shared__ float Xs[64 * 33];

    int lb = blockIdx.x & 1;
    int tmp = blockIdx.x >> 1;
    int nb = tmp & (NBLK - 1);
    int b = tmp / NBLK;

    const float* W = (LAYER == 1) ? g_w1 : (LAYER == 2) ? g_w2 : (LAYER == 3) ? g_w3 : g_w4;
    const float* in = (LAYER == 1) ? extin : (LAYER == 2) ? g_ea : (LAYER == 3) ? g_eb : g_ea;

    const float* Wb = W + ((size_t)b * N + nb * 128) * K;
    const float* Ib = in + ((size_t)b * LL + lb * 64) * K;

    int tid = threadIdx.x;
    int tc = tid & 31, tr = tid >> 5;

    float acc[8][4];
#pragma unroll
    for (int i = 0; i < 8; i++)
#pragma unroll
        for (int d = 0; d < 4; d++) acc[i][d] = 0.f;

    for (int kc = 0; kc < K; kc += 32) {
#pragma unroll
        for (int s = 0; s < 16; s++) {
            int e = tid + s * 256;
            int kk = e & 31, n = e >> 5;
            Ws[kk * 129 + n] = Wb[(size_t)n * K + kc + kk];
        }
#pragma unroll
        for (int s = 0; s < 8; s++) {
            int e = tid + s * 256;
            int kk = e & 31, l = e >> 5;
            Xs[l * 33 + kk] = Ib[(size_t)l * K + kc + kk];
        }
        __syncthreads();
#pragma unroll
        for (int kk = 0; kk < 32; kk++) {
            float w0 = Ws[kk * 129 + tc];
            float w1 = Ws[kk * 129 + tc + 32];
            float w2 = Ws[kk * 129 + tc + 64];
            float w3 = Ws[kk * 129 + tc + 96];
#pragma unroll
            for (int i = 0; i < 8; i++) {
                float xv = Xs[(tr * 8 + i) * 33 + kk];
                acc[i][0] = fmaf(xv, w0, acc[i][0]);
                acc[i][1] = fmaf(xv, w1, acc[i][1]);
                acc[i][2] = fmaf(xv, w2, acc[i][2]);
                acc[i][3] = fmaf(xv, w3, acc[i][3]);
            }
        }
        __syncthreads();
    }

    float bv[4] = {0.f, 0.f, 0.f, 0.f};
    if (LAYER != 4) {
        const float* bias = (LAYER == 1) ? g_b1 : (LAYER == 2) ? g_b2 : g_b3;
#pragma unroll
        for (int d = 0; d < 4; d++) bv[d] = bias[b * HH + nb * 128 + tc + 32 * d];
    }
    float* op = (LAYER == 4) ? outp : (LAYER == 1) ? g_ea : (LAYER == 2) ? g_eb : g_ea;

#pragma unroll
    for (int i = 0; i < 8; i++) {
        int l = lb * 64 + tr * 8 + i;
        size_t rowo = ((size_t)b * LL + l) * N + nb * 128;
#pragma unroll
        for (int d = 0; d < 4; d++) {
            float v = acc[i][d];
            if (LAYER != 4) v = fmaxf(v + bv[d], 0.f);
            if (LAYER == 3) v *= gate[((size_t)b * LL + l) * HH + nb * 128 + tc + 32 * d];
            op[rowo + tc + 32 * d] = v;
        }
    }
}

// ---------------- final loss + scalar outputs ----------------------------------
__global__ void k_loss(const float* __restrict__ ty, const float* __restrict__ loglr,
                       float* __restrict__ out) {
    int gw = (blockIdx.x * blockDim.x + threadIdx.x) >> 5;
    int lane = threadIdx.x & 31;
    if (gw >= BB * LL) return;
    const float* lg = out + 4097 + (size_t)gw * YY;  // logits written by k_eval<4>
    const float* tyv = ty + (size_t)gw * YY;
    float acc = 0.f;
#pragma unroll
    for (int k = lane, it = 0; it < YY / 32; it++, k += 32) {
        float d = lg[k] - tyv[k];
        acc = fmaf(d, d, acc);
    }
    acc = warp_sum(acc);
    if (lane == 0) {
        float m = acc * (1.f / (float)YY);
        out[gw] = m;             // loss [B,L,1]
        out[2049 + gw] = m;      // evaluation [(B L)]
    }
    if (gw == 0 && lane == 0) out[2048] = expf(*loglr);  // inner_lr
}

// ---------------- launch --------------------------------------------------------
extern "C" void kernel_launch(void* const* d_in, const int* in_sizes, int n_in,
                              void* d_out, int out_size) {
    const float* train_x = (const float*)d_in[0];
    const float* train_y = (const float*)d_in[1];
    const float* test_x = (const float*)d_in[2];
    const float* test_y = (const float*)d_in[3];
    const float* train_gate = (const float*)d_in[4];
    const float* test_gate = (const float*)d_in[5];
    const float* fc1 = (const float*)d_in[6];
    const float* b1 = (const float*)d_in[7];
    const float* fc2 = (const float*)d_in[8];
    const float* b2 = (const float*)d_in[9];
    const float* fc3 = (const float*)d_in[10];
    const float* b3 = (const float*)d_in[11];
    const float* fc4 = (const float*)d_in[12];
    const float* loglr = (const float*)d_in[13];
    float* out = (float*)d_out;

    k_init<<<1024, 256>>>(fc1, b1, fc2, b2, fc3, b3, fc4);

    for (int t = 0; t < TT; t++) {
        k_fwd1<<<1024, 256>>>(train_x, t);
        k_fwd2<<<1024, 256>>>();
        k_fwd3<<<1024, 256>>>(train_gate, t);
        k_fwd4<<<512, 256>>>(train_y, t);
        k_bwd4<<<64, 256>>>(train_gate, loglr, t);
        k_bwd3<<<64, 256>>>(loglr);
        k_bwd2<<<64, 256>>>(train_x, loglr, t);
    }

    // eval forward with adapted weights
    k_eval<1><<<BB * (HH / 128) * 2, 256>>>(test_x, nullptr, nullptr);
    k_eval<2><<<BB * (HH / 128) * 2, 256>>>(nullptr, nullptr, nullptr);
    k_eval<3><<<BB * (HH / 128) * 2, 256>>>(nullptr, test_gate, nullptr);
    k_eval<4><<<BB * (YY / 128) * 2, 256>>>(nullptr, nullptr, out + 4097);

    k_loss<<<256, 256>>>(test_y, loglr, out);
}

// round 3
// speedup vs baseline: 1.0126x; 1.0126x over previous
#include <cuda_runtime.h>
#include <math.h>

#define BB 16
#define TT 16
#define LL 128
#define XX 256
#define HH 512
#define YY 256

// ---------------- device scratch (static allocation; no runtime alloc) ----------------
__device__ __align__(16) float g_w1[BB * HH * XX];   // 8 MB
__device__ __align__(16) float g_w2[BB * HH * HH];   // 16 MB
__device__ __align__(16) float g_w3[BB * HH * HH];   // 16 MB
__device__ __align__(16) float g_w4[BB * YY * HH];   // 8 MB
__device__ __align__(16) float g_b1[BB * HH];
__device__ __align__(16) float g_b2[BB * HH];
__device__ __align__(16) float g_b3[BB * HH];

__device__ __align__(16) float g_h1[BB * HH];
__device__ __align__(16) float g_h2[BB * HH];
__device__ __align__(16) float g_h3[BB * HH];
__device__ __align__(16) float g_hg[BB * HH];
__device__ __align__(16) float g_dlogit[BB * YY];
__device__ __align__(16) float g_dz3[BB * HH];
__device__ __align__(16) float g_dz2[BB * HH];

__device__ __align__(16) float g_ea[BB * LL * HH];   // 4 MB eval ping
__device__ __align__(16) float g_eb[BB * LL * HH];   // 4 MB eval pong

// ---------------- helpers ----------------
__device__ __forceinline__ float warp_sum(float v) {
    v += __shfl_xor_sync(0xffffffffu, v, 16);
    v += __shfl_xor_sync(0xffffffffu, v, 8);
    v += __shfl_xor_sync(0xffffffffu, v, 4);
    v += __shfl_xor_sync(0xffffffffu, v, 2);
    v += __shfl_xor_sync(0xffffffffu, v, 1);
    return v;
}

// ---------------- init: broadcast shared params into per-example fast weights ----------
__global__ void k_init(const float* __restrict__ fc1, const float* __restrict__ b1,
                       const float* __restrict__ fc2, const float* __restrict__ b2,
                       const float* __restrict__ fc3, const float* __restrict__ b3,
                       const float* __restrict__ fc4) {
    int stride = gridDim.x * blockDim.x;
    int i0 = blockIdx.x * blockDim.x + threadIdx.x;
    for (int i = i0; i < BB * HH * XX; i += stride) g_w1[i] = fc1[i & (HH * XX - 1)];
    for (int i = i0; i < BB * HH * HH; i += stride) g_w2[i] = fc2[i & (HH * HH - 1)];
    for (int i = i0; i < BB * HH * HH; i += stride) g_w3[i] = fc3[i & (HH * HH - 1)];
    for (int i = i0; i < BB * YY * HH; i += stride) g_w4[i] = fc4[i & (YY * HH - 1)];
    for (int i = i0; i < BB * HH; i += stride) {
        g_b1[i] = b1[i & (HH - 1)];
        g_b2[i] = b2[i & (HH - 1)];
        g_b3[i] = b3[i & (HH - 1)];
    }
}

// ---------------- training forward: one warp per output row -------------------
__global__ void k_fwd1(const float* __restrict__ tx, int t) {
    int gw = (blockIdx.x * blockDim.x + threadIdx.x) >> 5;
    int lane = threadIdx.x & 31;
    int b = gw >> 9, r = gw & 511;
    const float4* w = reinterpret_cast<const float4*>(g_w1 + ((size_t)b * HH + r) * XX);
    const float4* xv = reinterpret_cast<const float4*>(tx + ((size_t)(b * TT + t)) * XX);
    float acc = 0.f;
#pragma unroll
    for (int k = lane, it = 0; it < XX / 128; it++, k += 32) {
        float4 a = w[k], c = xv[k];
        acc += a.x * c.x + a.y * c.y + a.z * c.z + a.w * c.w;
    }
    acc = warp_sum(acc);
    if (lane == 0) {
        float z = acc + g_b1[b * HH + r];
        g_h1[b * HH + r] = fmaxf(z, 0.f);
    }
}

__global__ void k_fwd2() {
    int gw = (blockIdx.x * blockDim.x + threadIdx.x) >> 5;
    int lane = threadIdx.x & 31;
    int b = gw >> 9, r = gw & 511;
    const float4* w = reinterpret_cast<const float4*>(g_w2 + ((size_t)b * HH + r) * HH);
    const float4* xv = reinterpret_cast<const float4*>(g_h1 + (size_t)b * HH);
    float acc = 0.f;
#pragma unroll
    for (int k = lane, it = 0; it < HH / 128; it++, k += 32) {
        float4 a = w[k], c = xv[k];
        acc += a.x * c.x + a.y * c.y + a.z * c.z + a.w * c.w;
    }
    acc = warp_sum(acc);
    if (lane == 0) {
        float z = acc + g_b2[b * HH + r];
        g_h2[b * HH + r] = fmaxf(z, 0.f);
    }
}

__global__ void k_fwd3(const float* __restrict__ tg, int t) {
    int gw = (blockIdx.x * blockDim.x + threadIdx.x) >> 5;
    int lane = threadIdx.x & 31;
    int b = gw >> 9, r = gw & 511;
    const float4* w = reinterpret_cast<const float4*>(g_w3 + ((size_t)b * HH + r) * HH);
    const float4* xv = reinterpret_cast<const float4*>(g_h2 + (size_t)b * HH);
    float acc = 0.f;
#pragma unroll
    for (int k = lane, it = 0; it < HH / 128; it++, k += 32) {
        float4 a = w[k], c = xv[k];
        acc += a.x * c.x + a.y * c.y + a.z * c.z + a.w * c.w;
    }
    acc = warp_sum(acc);
    if (lane == 0) {
        float z = acc + g_b3[b * HH + r];
        float h3 = fmaxf(z, 0.f);
        g_h3[b * HH + r] = h3;
        g_hg[b * HH + r] = h3 * tg[((size_t)(b * TT + t)) * HH + r];
    }
}

__global__ void k_fwd4(const float* __restrict__ ty, int t) {
    int gw = (blockIdx.x * blockDim.x + threadIdx.x) >> 5;
    int lane = threadIdx.x & 31;
    int b = gw >> 8, r = gw & 255;
    const float4* w = reinterpret_cast<const float4*>(g_w4 + ((size_t)b * YY + r) * HH);
    const float4* xv = reinterpret_cast<const float4*>(g_hg + (size_t)b * HH);
    float acc = 0.f;
#pragma unroll
    for (int k = lane, it = 0; it < HH / 128; it++, k += 32) {
        float4 a = w[k], c = xv[k];
        acc += a.x * c.x + a.y * c.y + a.z * c.z + a.w * c.w;
    }
    acc = warp_sum(acc);
    if (lane == 0) {
        float yv = ty[((size_t)(b * TT + t)) * YY + r];
        g_dlogit[b * YY + r] = (2.f / (float)YY) * (acc - yv);
    }
}

// ---------------- backward (transposed matvec + weight update, fused) ---------
// grid: 16 examples * 4 column-chunks of 128; block: 256 threads (i-range split in half)
__global__ void k_bwd4(const float* __restrict__ tg, const float* __restrict__ loglr, int t) {
    int b = blockIdx.x >> 2, jc = blockIdx.x & 3;
    int tid = threadIdx.x;
    int j = (jc << 7) + (tid & 127);
    int half = tid >> 7;
    __shared__ float s_dl[YY];
    __shared__ float s_acc[256];
    for (int i = tid; i < YY; i += 256) s_dl[i] = g_dlogit[b * YY + i];
    __syncthreads();
    float lr = expf(*loglr);
    float hgj = g_hg[b * HH + j];
    float* wp = g_w4 + (size_t)b * (YY * HH) + j;
    float acc = 0.f;
    int i0 = half * (YY / 2);
#pragma unroll 16
    for (int i = i0; i < i0 + YY / 2; i++) {
        float w = wp[(size_t)i * HH];
        float dl = s_dl[i];
        acc = fmaf(w, dl, acc);
        wp[(size_t)i * HH] = fmaf(-lr * dl, hgj, w);
    }
    s_acc[tid] = acc;
    __syncthreads();
    if (half == 0) {
        float dhg = s_acc[tid] + s_acc[tid + 128];
        float gatev = tg[((size_t)(b * TT + t)) * HH + j];
        float h3 = g_h3[b * HH + j];
        float dz3 = (h3 > 0.f) ? dhg * gatev : 0.f;
        g_dz3[b * HH + j] = dz3;
        g_b3[b * HH + j] = g_b3[b * HH + j] - lr * dz3;
    }
}

__global__ void k_bwd3(const float* __restrict__ loglr) {
    int b = blockIdx.x >> 2, jc = blockIdx.x & 3;
    int tid = threadIdx.x;
    int j = (jc << 7) + (tid & 127);
    int half = tid >> 7;
    __shared__ float s_dz[HH];
    __shared__ float s_acc[256];
    for (int i = tid; i < HH; i += 256) s_dz[i] = g_dz3[b * HH + i];
    __syncthreads();
    float lr = expf(*loglr);
    float h2j = g_h2[b * HH + j];
    float* wp = g_w3 + (size_t)b * (HH * HH) + j;
    float acc = 0.f;
    int i0 = half * (HH / 2);
#pragma unroll 16
    for (int i = i0; i < i0 + HH / 2; i++) {
        float w = wp[(size_t)i * HH];
        float dz = s_dz[i];
        acc = fmaf(w, dz, acc);
        wp[(size_t)i * HH] = fmaf(-lr * dz, h2j, w);
    }
    s_acc[tid] = acc;
    __syncthreads();
    if (half == 0) {
        float dh2 = s_acc[tid] + s_acc[tid + 128];
        float dz2 = (h2j > 0.f) ? dh2 : 0.f;
        g_dz2[b * HH + j] = dz2;
        g_b2[b * HH + j] = g_b2[b * HH + j] - lr * dz2;
    }
}

__global__ void k_bwd2(const float* __restrict__ tx, const float* __restrict__ loglr, int t) {
    int b = blockIdx.x >> 2, jc = blockIdx.x & 3;
    int tid = threadIdx.x;
    int j = (jc << 7) + (tid & 127);
    int half = tid >> 7;
    __shared__ float s_dz[HH];
    __shared__ float s_acc[256];
    __shared__ float s_dz1[128];
    __shared__ __align__(16) float s_x[XX];
    for (int i = tid; i < HH; i += 256) s_dz[i] = g_dz2[b * HH + i];
    for (int k = tid; k < XX; k += 256) s_x[k] = tx[((size_t)(b * TT + t)) * XX + k];
    __syncthreads();
    float lr = expf(*loglr);
    float h1j = g_h1[b * HH + j];
    float* wp = g_w2 + (size_t)b * (HH * HH) + j;
    float acc = 0.f;
    int i0 = half * (HH / 2);
#pragma unroll 16
    for (int i = i0; i < i0 + HH / 2; i++) {
        float w = wp[(size_t)i * HH];
        float dz = s_dz[i];
        acc = fmaf(w, dz, acc);
        wp[(size_t)i * HH] = fmaf(-lr * dz, h1j, w);
    }
    s_acc[tid] = acc;
    __syncthreads();
    if (half == 0) {
        float dh1 = s_acc[tid] + s_acc[tid + 128];
        float dz1 = (h1j > 0.f) ? dh1 : 0.f;
        g_b1[b * HH + j] = g_b1[b * HH + j] - lr * dz1;
        s_dz1[tid] = dz1;  // tid < 128 here
    }
    __syncthreads();
    // fc1 slab update for hidden rows [jc*128, jc*128+128)
    float4* w1 = reinterpret_cast<float4*>(g_w1 + ((size_t)b * HH + (jc << 7)) * XX);
    const float4* sx4 = reinterpret_cast<const float4*>(s_x);
#pragma unroll 8
    for (int e = tid; e < 128 * (XX / 4); e += 256) {
        int r = e >> 6;
        int k4 = e & 63;
        float c = lr * s_dz1[r];
        float4 w = w1[e];
        float4 xv = sx4[k4];
        w.x -= c * xv.x; w.y -= c * xv.y; w.z -= c * xv.z; w.w -= c * xv.w;
        w1[e] = w;
    }
}

// ---------------- eval: tiled fp32 GEMM per layer ------------------------------
// block: 256 threads computing [128 n x 64 l] per (b, nb, lb) tile.
template <int LAYER>
__global__ void __launch_bounds__(256) k_eval(const float* __restrict__ extin,
                                              const float* __restrict__ gate,
                                              float* __restrict__ outp) {
    constexpr int N = (LAYER == 4) ? YY : HH;
    constexpr int K = (LAYER == 1) ? XX : HH;
    constexpr int NBLK = N / 128;

    __shared__ float Ws[32 * 129];
    __shared__ float Xs[64 * 33];

    int lb = blockIdx.x & 1;
    int tmp = blockIdx.x >> 1;
    int nb = tmp & (NBLK - 1);
    int b = tmp / NBLK;

    const float* W = (LAYER == 1) ? g_w1 : (LAYER == 2) ? g_w2 : (LAYER == 3) ? g_w3 : g_w4;
    const float* in = (LAYER == 1) ? extin : (LAYER == 2) ? g_ea : (LAYER == 3) ? g_eb : g_ea;

    const float* Wb = W + ((size_t)b * N + nb * 128) * K;
    const float* Ib = in + ((size_t)b * LL + lb * 64) * K;

    int tid = threadIdx.x;
    int tc = tid & 31, tr = tid >> 5;

    float acc[8][4];
#pragma unroll
    for (int i = 0; i < 8; i++)
#pragma unroll
        for (int d = 0; d < 4; d++) acc[i][d] = 0.f;

    for (int kc = 0; kc < K; kc += 32) {
#pragma unroll
        for (int s = 0; s < 16; s++) {
            int e = tid + s * 256;
            int kk = e & 31, n = e >> 5;
            Ws[kk * 129 + n] = Wb[(size_t)n * K + kc + kk];
        }
#pragma unroll
        for (int s = 0; s < 8; s++) {
            int e = tid + s * 256;
            int kk = e & 31, l = e >> 5;
            Xs[l * 33 + kk] = Ib[(size_t)l * K + kc + kk];
        }
        __syncthreads();
#pragma unroll
        for (int kk = 0; kk < 32; kk++) {
            float w0 = Ws[kk * 129 + tc];
            float w1 = Ws[kk * 129 + tc + 32];
            float w2 = Ws[kk * 129 + tc + 64];
            float w3 = Ws[kk * 129 + tc + 96];
#pragma unroll
            for (int i = 0; i < 8; i++) {
                float xv = Xs[(tr * 8 + i) * 33 + kk];
                acc[i][0] = fmaf(xv, w0, acc[i][0]);
                acc[i][1] = fmaf(xv, w1, acc[i][1]);
                acc[i][2] = fmaf(xv, w2, acc[i][2]);
                acc[i][3] = fmaf(xv, w3, acc[i][3]);
            }
        }
        __syncthreads();
    }

    float bv[4] = {0.f, 0.f, 0.f, 0.f};
    if (LAYER != 4) {
        const float* bias = (LAYER == 1) ? g_b1 : (LAYER == 2) ? g_b2 : g_b3;
#pragma unroll
        for (int d = 0; d < 4; d++) bv[d] = bias[b * HH + nb * 128 + tc + 32 * d];
    }
    float* op = (LAYER == 4) ? outp : (LAYER == 1) ? g_ea : (LAYER == 2) ? g_eb : g_ea;

#pragma unroll
    for (int i = 0; i < 8; i++) {
        int l = lb * 64 + tr * 8 + i;
        size_t rowo = ((size_t)b * LL + l) * N + nb * 128;
#pragma unroll
        for (int d = 0; d < 4; d++) {
            float v = acc[i][d];
            if (LAYER != 4) v = fmaxf(v + bv[d], 0.f);
            if (LAYER == 3) v *= gate[((size_t)b * LL + l) * HH + nb * 128 + tc + 32 * d];
            op[rowo + tc + 32 * d] = v;
        }
    }
}

// ---------------- final loss + scalar outputs ----------------------------------
__global__ void k_loss(const float* __restrict__ ty, const float* __restrict__ loglr,
                       float* __restrict__ out) {
    int gw = (blockIdx.x * blockDim.x + threadIdx.x) >> 5;
    int lane = threadIdx.x & 31;
    if (gw >= BB * LL) return;
    const float* lg = out + 4097 + (size_t)gw * YY;  // logits written by k_eval<4>
    const float* tyv = ty + (size_t)gw * YY;
    float acc = 0.f;
#pragma unroll
    for (int k = lane, it = 0; it < YY / 32; it++, k += 32) {
        float d = lg[k] - tyv[k];
        acc = fmaf(d, d, acc);
    }
    acc = warp_sum(acc);
    if (lane == 0) {
        float m = acc * (1.f / (float)YY);
        out[gw] = m;             // loss [B,L,1]
        out[2049 + gw] = m;      // evaluation [(B L)]
    }
    if (gw == 0 && lane == 0) out[2048] = expf(*loglr);  // inner_lr
}

// ---------------- launch --------------------------------------------------------
extern "C" void kernel_launch(void* const* d_in, const int* in_sizes, int n_in,
                              void* d_out, int out_size) {
    const float* train_x = (const float*)d_in[0];
    const float* train_y = (const float*)d_in[1];
    const float* test_x = (const float*)d_in[2];
    const float* test_y = (const float*)d_in[3];
    const float* train_gate = (const float*)d_in[4];
    const float* test_gate = (const float*)d_in[5];
    const float* fc1 = (const float*)d_in[6];
    const float* b1 = (const float*)d_in[7];
    const float* fc2 = (const float*)d_in[8];
    const float* b2 = (const float*)d_in[9];
    const float* fc3 = (const float*)d_in[10];
    const float* b3 = (const float*)d_in[11];
    const float* fc4 = (const float*)d_in[12];
    const float* loglr = (const float*)d_in[13];
    float* out = (float*)d_out;

    k_init<<<1024, 256>>>(fc1, b1, fc2, b2, fc3, b3, fc4);

    for (int t = 0; t < TT; t++) {
        k_fwd1<<<1024, 256>>>(train_x, t);
        k_fwd2<<<1024, 256>>>();
        k_fwd3<<<1024, 256>>>(train_gate, t);
        k_fwd4<<<512, 256>>>(train_y, t);
        k_bwd4<<<64, 256>>>(train_gate, loglr, t);
        k_bwd3<<<64, 256>>>(loglr);
        k_bwd2<<<64, 256>>>(train_x, loglr, t);
    }

    // eval forward with adapted weights
    k_eval<1><<<BB * (HH / 128) * 2, 256>>>(test_x, nullptr, nullptr);
    k_eval<2><<<BB * (HH / 128) * 2, 256>>>(nullptr, nullptr, nullptr);
    k_eval<3><<<BB * (HH / 128) * 2, 256>>>(nullptr, test_gate, nullptr);
    k_eval<4><<<BB * (YY / 128) * 2, 256>>>(nullptr, nullptr, out + 4097);

    k_loss<<<256, 256>>>(test_y, loglr, out);
}

// round 4
// speedup vs baseline: 1.2369x; 1.2215x over previous
#include <cuda_runtime.h>
#include <math.h>

#define BB 16
#define TT 16
#define LL 128
#define XX 256
#define HH 512
#define YY 256
#define RCTA 8
#define TPB 512

// materialized adapted weights (eval)
__device__ __align__(16) float g_w1[BB * HH * XX];
__device__ __align__(16) float g_w2[BB * HH * HH];
__device__ __align__(16) float g_w3[BB * HH * HH];
__device__ __align__(16) float g_w4[BB * YY * HH];
__device__ __align__(16) float g_b1[BB * HH];
__device__ __align__(16) float g_b2[BB * HH];
__device__ __align__(16) float g_b3[BB * HH];
// W0 transposes for backward
__device__ __align__(16) float g_w2T[HH * HH];
__device__ __align__(16) float g_w3T[HH * HH];
__device__ __align__(16) float g_w4T[HH * YY];
// histories, layout [b][s][dim]
__device__ __align__(16) float g_h1A[BB * TT * HH];
__device__ __align__(16) float g_h2A[BB * TT * HH];
__device__ __align__(16) float g_h3A[BB * TT * HH];
__device__ __align__(16) float g_hgA[BB * TT * HH];
__device__ __align__(16) float g_dz1A[BB * TT * HH];
__device__ __align__(16) float g_dz2A[BB * TT * HH];
__device__ __align__(16) float g_dz3A[BB * TT * HH];
__device__ __align__(16) float g_dlA[BB * TT * YY];
__device__ __align__(16) float g_xg[BB * TT * TT];
// eval ping-pong
__device__ __align__(16) float g_ea[BB * LL * HH];
__device__ __align__(16) float g_eb[BB * LL * HH];

__device__ __forceinline__ float warp_sum(float v) {
    v += __shfl_xor_sync(0xffffffffu, v, 16);
    v += __shfl_xor_sync(0xffffffffu, v, 8);
    v += __shfl_xor_sync(0xffffffffu, v, 4);
    v += __shfl_xor_sync(0xffffffffu, v, 2);
    v += __shfl_xor_sync(0xffffffffu, v, 1);
    return v;
}

__device__ __forceinline__ void csync() {
    asm volatile("barrier.cluster.arrive.aligned;" ::: "memory");
    asm volatile("barrier.cluster.wait.aligned;" ::: "memory");
}

// ---------------- pre-pass: transposes ----------------
__global__ void __launch_bounds__(256) k_tr(const float* __restrict__ fc2,
                                            const float* __restrict__ fc3,
                                            const float* __restrict__ fc4) {
    __shared__ float tile[32][33];
    int bid = blockIdx.x;
    const float* src;
    float* dst;
    int RS, CS;
    if (bid < 256) { src = fc2; dst = g_w2T; RS = HH; CS = HH; }
    else if (bid < 512) { src = fc3; dst = g_w3T; bid -= 256; RS = HH; CS = HH; }
    else { src = fc4; dst = g_w4T; bid -= 512; RS = YY; CS = HH; }
    int tpr = CS / 32;
    int r0 = (bid / tpr) * 32, c0 = (bid % tpr) * 32;
    int tx = threadIdx.x & 31, ty = threadIdx.x >> 5;
    for (int i = ty; i < 32; i += 8) tile[i][tx] = src[(size_t)(r0 + i) * CS + c0 + tx];
    __syncthreads();
    for (int i = ty; i < 32; i += 8) dst[(size_t)(c0 + i) * RS + r0 + tx] = tile[tx][i];
}

// ---------------- pre-pass: biases + x-gram ----------------
__global__ void __launch_bounds__(256) k_misc(const float* __restrict__ b1,
                                              const float* __restrict__ b2,
                                              const float* __restrict__ b3,
                                              const float* __restrict__ tx) {
    int gt = blockIdx.x * blockDim.x + threadIdx.x;
    int NT = gridDim.x * blockDim.x;
    for (int i = gt; i < BB * HH; i += NT) {
        int k = i & (HH - 1);
        g_b1[i] = b1[k]; g_b2[i] = b2[k]; g_b3[i] = b3[k];
    }
    int gw = gt >> 5, lane = gt & 31;
    for (int d = gw; d < BB * TT * TT; d += NT >> 5) {
        int b = d >> 8, s1 = (d >> 4) & 15, s2 = d & 15;
        const float4* xa = (const float4*)(tx + (size_t)(b * TT + s1) * XX);
        const float4* xb = (const float4*)(tx + (size_t)(b * TT + s2) * XX);
        float4 a = xa[lane], c = xb[lane];
        float acc = a.x * c.x + a.y * c.y + a.z * c.z + a.w * c.w;
        a = xa[lane + 32]; c = xb[lane + 32];
        acc += a.x * c.x + a.y * c.y + a.z * c.z + a.w * c.w;
        acc = warp_sum(acc);
        if (lane == 0) g_xg[d] = acc;
    }
}

// octet (8 lanes) computes row-n dot against both examples' smem vectors
template <int K>
__device__ __forceinline__ void omv(const float* __restrict__ W, int n,
                                    const float* s_x, int l8, float& a0, float& a1) {
    const float4* w4 = (const float4*)(W + (size_t)n * K);
    const float4* x0 = (const float4*)(s_x);
    const float4* x1 = (const float4*)(s_x + (K + 4));
    a0 = 0.f; a1 = 0.f;
#pragma unroll
    for (int j = l8; j < K / 4; j += 8) {
        float4 w = w4[j];
        float4 p = x0[j], q = x1[j];
        a0 = fmaf(w.x, p.x, a0); a0 = fmaf(w.y, p.y, a0);
        a0 = fmaf(w.z, p.z, a0); a0 = fmaf(w.w, p.w, a0);
        a1 = fmaf(w.x, q.x, a1); a1 = fmaf(w.y, q.y, a1);
        a1 = fmaf(w.z, q.z, a1); a1 = fmaf(w.w, q.w, a1);
    }
}

__device__ __forceinline__ void ored(float& a0, float& a1) {
#pragma unroll
    for (int m = 1; m < 8; m <<= 1) {
        a0 += __shfl_xor_sync(0xffffffffu, a0, m);
        a1 += __shfl_xor_sync(0xffffffffu, a1, m);
    }
}

// low-rank correction: a_b -= sum_{s<t} c[b][s] * uA[b][s][n]
template <int NOUT>
__device__ __forceinline__ void corr(const float* __restrict__ uA, int b0, int n,
                                     const float* s_c, int t, int l8,
                                     float& a0, float& a1) {
#pragma unroll
    for (int s = l8; s < TT; s += 8) {
        if (s < t) {
            a0 -= s_c[s] * __ldcg(uA + (size_t)(b0 * TT + s) * NOUT + n);
            a1 -= s_c[16 + s] * __ldcg(uA + (size_t)((b0 + 1) * TT + s) * NOUT + n);
        }
    }
}

// load current vectors (slot t) into smem + compute dot coefficients
template <int K>
__device__ __forceinline__ void stage(const float* __restrict__ curA, float* s_x,
                                      float* s_c, int b0, int t, int tid, float lr) {
    for (int i = tid; i < (K / 4) * 2; i += TPB) {
        int b = i >= K / 4;
        int j = i - b * (K / 4);
        float4 v = __ldcg(((const float4*)(curA + (size_t)((b0 + b) * TT + t) * K)) + j);
        *((float4*)(s_x + b * (K + 4)) + j) = v;
    }
    __syncthreads();
    int wid = tid >> 5, lane = tid & 31;
    for (int p = wid; p < 2 * t; p += TPB / 32) {
        int b = p & 1, s = p >> 1;
        const float4* v4 = (const float4*)(curA + (size_t)((b0 + b) * TT + s) * K);
        const float4* c4 = (const float4*)(s_x + b * (K + 4));
        float acc = 0.f;
        for (int j = lane; j < K / 4; j += 32) {
            float4 v = __ldcg(v4 + j);
            float4 c = c4[j];
            acc += v.x * c.x + v.y * c.y + v.z * c.z + v.w * c.w;
        }
        acc = warp_sum(acc);
        if (lane == 0) s_c[b * 16 + s] = lr * acc;
    }
    __syncthreads();
}

// ---------------- training: 8 clusters x 8 CTAs, 2 examples per cluster --------
__global__ void __cluster_dims__(RCTA, 1, 1) __launch_bounds__(TPB, 1)
k_train(const float* __restrict__ tx, const float* __restrict__ ty,
        const float* __restrict__ tg,
        const float* __restrict__ fc1, const float* __restrict__ fc2,
        const float* __restrict__ fc3, const float* __restrict__ fc4,
        const float* __restrict__ loglr) {
    __shared__ __align__(16) float s_x[2 * (HH + 4)];
    __shared__ float s_c[32];
    int tid = threadIdx.x;
    int r = blockIdx.x & (RCTA - 1);
    int b0 = (blockIdx.x / RCTA) * 2;
    int l8 = tid & 7;
    int oct = tid >> 3;  // 0..63
    float lr = expf(*loglr);

    for (int t = 0; t < TT; t++) {
        // ---- fwd1 ----
        csync();
        for (int i = tid; i < (XX / 4) * 2; i += TPB) {
            int b = i >= XX / 4;
            int j = i - b * (XX / 4);
            float4 v = ((const float4*)(tx + (size_t)((b0 + b) * TT + t) * XX))[j];
            *((float4*)(s_x + b * (XX + 4)) + j) = v;
        }
        if (tid < 32) {
            int b = tid >> 4, s = tid & 15;
            s_c[tid] = (s < t) ? lr * g_xg[((b0 + b) * TT + s) * TT + t] : 0.f;
        }
        __syncthreads();
        {
            int n = r * 64 + oct;
            float a0, a1;
            omv<XX>(fc1, n, s_x, l8, a0, a1);
            corr<HH>(g_dz1A, b0, n, s_c, t, l8, a0, a1);
            ored(a0, a1);
            if (l8 == 0) {
                g_h1A[(size_t)(b0 * TT + t) * HH + n] = fmaxf(a0 + g_b1[b0 * HH + n], 0.f);
                g_h1A[(size_t)((b0 + 1) * TT + t) * HH + n] = fmaxf(a1 + g_b1[(b0 + 1) * HH + n], 0.f);
            }
        }
        // ---- fwd2 ----
        csync();
        stage<HH>(g_h1A, s_x, s_c, b0, t, tid, lr);
        {
            int n = r * 64 + oct;
            float a0, a1;
            omv<HH>(fc2, n, s_x, l8, a0, a1);
            corr<HH>(g_dz2A, b0, n, s_c, t, l8, a0, a1);
            ored(a0, a1);
            if (l8 == 0) {
                g_h2A[(size_t)(b0 * TT + t) * HH + n] = fmaxf(a0 + g_b2[b0 * HH + n], 0.f);
                g_h2A[(size_t)((b0 + 1) * TT + t) * HH + n] = fmaxf(a1 + g_b2[(b0 + 1) * HH + n], 0.f);
            }
        }
        // ---- fwd3 + gate ----
        csync();
        stage<HH>(g_h2A, s_x, s_c, b0, t, tid, lr);
        {
            int n = r * 64 + oct;
            float a0, a1;
            omv<HH>(fc3, n, s_x, l8, a0, a1);
            corr<HH>(g_dz3A, b0, n, s_c, t, l8, a0, a1);
            ored(a0, a1);
            if (l8 == 0) {
                float h30 = fmaxf(a0 + g_b3[b0 * HH + n], 0.f);
                float h31 = fmaxf(a1 + g_b3[(b0 + 1) * HH + n], 0.f);
                g_h3A[(size_t)(b0 * TT + t) * HH + n] = h30;
                g_h3A[(size_t)((b0 + 1) * TT + t) * HH + n] = h31;
                g_hgA[(size_t)(b0 * TT + t) * HH + n] = h30 * tg[(size_t)(b0 * TT + t) * HH + n];
                g_hgA[(size_t)((b0 + 1) * TT + t) * HH + n] = h31 * tg[(size_t)((b0 + 1) * TT + t) * HH + n];
            }
        }
        // ---- fwd4 -> dlogit ----
        csync();
        stage<HH>(g_hgA, s_x, s_c, b0, t, tid, lr);
        if (oct < 32) {
            int n = r * 32 + oct;
            float a0, a1;
            omv<HH>(fc4, n, s_x, l8, a0, a1);
            corr<YY>(g_dlA, b0, n, s_c, t, l8, a0, a1);
            ored(a0, a1);
            if (l8 == 0) {
                g_dlA[(size_t)(b0 * TT + t) * YY + n] =
                    (2.f / (float)YY) * (a0 - ty[(size_t)(b0 * TT + t) * YY + n]);
                g_dlA[(size_t)((b0 + 1) * TT + t) * YY + n] =
                    (2.f / (float)YY) * (a1 - ty[(size_t)((b0 + 1) * TT + t) * YY + n]);
            }
        }
        // ---- bwd4: dhg -> dz3, b3 update ----
        csync();
        stage<YY>(g_dlA, s_x, s_c, b0, t, tid, lr);
        {
            int n = r * 64 + oct;
            float a0, a1;
            omv<YY>(g_w4T, n, s_x, l8, a0, a1);
            corr<HH>(g_hgA, b0, n, s_c, t, l8, a0, a1);
            ored(a0, a1);
            if (l8 == 0) {
                float h30 = g_h3A[(size_t)(b0 * TT + t) * HH + n];
                float h31 = g_h3A[(size_t)((b0 + 1) * TT + t) * HH + n];
                float d0 = (h30 > 0.f) ? a0 * tg[(size_t)(b0 * TT + t) * HH + n] : 0.f;
                float d1 = (h31 > 0.f) ? a1 * tg[(size_t)((b0 + 1) * TT + t) * HH + n] : 0.f;
                g_dz3A[(size_t)(b0 * TT + t) * HH + n] = d0;
                g_dz3A[(size_t)((b0 + 1) * TT + t) * HH + n] = d1;
                g_b3[b0 * HH + n] -= lr * d0;
                g_b3[(b0 + 1) * HH + n] -= lr * d1;
            }
        }
        // ---- bwd3: dh2 -> dz2, b2 update ----
        csync();
        stage<HH>(g_dz3A, s_x, s_c, b0, t, tid, lr);
        {
            int n = r * 64 + oct;
            float a0, a1;
            omv<HH>(g_w3T, n, s_x, l8, a0, a1);
            corr<HH>(g_h2A, b0, n, s_c, t, l8, a0, a1);
            ored(a0, a1);
            if (l8 == 0) {
                float h20 = g_h2A[(size_t)(b0 * TT + t) * HH + n];
                float h21 = g_h2A[(size_t)((b0 + 1) * TT + t) * HH + n];
                float d0 = (h20 > 0.f) ? a0 : 0.f;
                float d1 = (h21 > 0.f) ? a1 : 0.f;
                g_dz2A[(size_t)(b0 * TT + t) * HH + n] = d0;
                g_dz2A[(size_t)((b0 + 1) * TT + t) * HH + n] = d1;
                g_b2[b0 * HH + n] -= lr * d0;
                g_b2[(b0 + 1) * HH + n] -= lr * d1;
            }
        }
        // ---- bwd2: dh1 -> dz1, b1 update ----
        csync();
        stage<HH>(g_dz2A, s_x, s_c, b0, t, tid, lr);
        {
            int n = r * 64 + oct;
            float a0, a1;
            omv<HH>(g_w2T, n, s_x, l8, a0, a1);
            corr<HH>(g_h1A, b0, n, s_c, t, l8, a0, a1);
            ored(a0, a1);
            if (l8 == 0) {
                float h10 = g_h1A[(size_t)(b0 * TT + t) * HH + n];
                float h11 = g_h1A[(size_t)((b0 + 1) * TT + t) * HH + n];
                float d0 = (h10 > 0.f) ? a0 : 0.f;
                float d1 = (h11 > 0.f) ? a1 : 0.f;
                g_dz1A[(size_t)(b0 * TT + t) * HH + n] = d0;
                g_dz1A[(size_t)((b0 + 1) * TT + t) * HH + n] = d1;
                g_b1[b0 * HH + n] -= lr * d0;
                g_b1[(b0 + 1) * HH + n] -= lr * d1;
            }
        }
    }
}

// ---------------- materialize adapted weights (rank-16) ------------------------
__global__ void __launch_bounds__(256) k_material(
    const float* __restrict__ fc1, const float* __restrict__ fc2,
    const float* __restrict__ fc3, const float* __restrict__ fc4,
    const float* __restrict__ tx, const float* __restrict__ loglr) {
    float lr = expf(*loglr);
    int NT = gridDim.x * blockDim.x;
    int t0 = blockIdx.x * blockDim.x + threadIdx.x;
    for (int i = t0; i < BB * HH * (XX / 4); i += NT) {
        int b = i >> 15, n = (i >> 6) & 511, k4 = i & 63;
        float4 acc = ((const float4*)fc1)[n * 64 + k4];
#pragma unroll
        for (int s = 0; s < TT; s++) {
            float u = lr * g_dz1A[(size_t)(b * TT + s) * HH + n];
            float4 v = ((const float4*)tx)[(b * TT + s) * 64 + k4];
            acc.x -= u * v.x; acc.y -= u * v.y; acc.z -= u * v.z; acc.w -= u * v.w;
        }
        ((float4*)g_w1)[i] = acc;
    }
    for (int i = t0; i < BB * HH * (HH / 4); i += NT) {
        int b = i >> 16, n = (i >> 7) & 511, k4 = i & 127;
        float4 acc = ((const float4*)fc2)[n * 128 + k4];
#pragma unroll
        for (int s = 0; s < TT; s++) {
            float u = lr * g_dz2A[(size_t)(b * TT + s) * HH + n];
            float4 v = ((const float4*)g_h1A)[(b * TT + s) * 128 + k4];
            acc.x -= u * v.x; acc.y -= u * v.y; acc.z -= u * v.z; acc.w -= u * v.w;
        }
        ((float4*)g_w2)[i] = acc;
    }
    for (int i = t0; i < BB * HH * (HH / 4); i += NT) {
        int b = i >> 16, n = (i >> 7) & 511, k4 = i & 127;
        float4 acc = ((const float4*)fc3)[n * 128 + k4];
#pragma unroll
        for (int s = 0; s < TT; s++) {
            float u = lr * g_dz3A[(size_t)(b * TT + s) * HH + n];
            float4 v = ((const float4*)g_h2A)[(b * TT + s) * 128 + k4];
            acc.x -= u * v.x; acc.y -= u * v.y; acc.z -= u * v.z; acc.w -= u * v.w;
        }
        ((float4*)g_w3)[i] = acc;
    }
    for (int i = t0; i < BB * YY * (HH / 4); i += NT) {
        int b = i >> 15, n = (i >> 7) & 255, k4 = i & 127;
        float4 acc = ((const float4*)fc4)[n * 128 + k4];
#pragma unroll
        for (int s = 0; s < TT; s++) {
            float u = lr * g_dlA[(size_t)(b * TT + s) * YY + n];
            float4 v = ((const float4*)g_hgA)[(b * TT + s) * 128 + k4];
            acc.x -= u * v.x; acc.y -= u * v.y; acc.z -= u * v.z; acc.w -= u * v.w;
        }
        ((float4*)g_w4)[i] = acc;
    }
}

// ---------------- eval: tiled fp32 GEMM per layer (proven in R1) ----------------
template <int LAYER>
__global__ void __launch_bounds__(256) k_eval(const float* __restrict__ extin,
                                              const float* __restrict__ gate,
                                              float* __restrict__ outp) {
    constexpr int N = (LAYER == 4) ? YY : HH;
    constexpr int K = (LAYER == 1) ? XX : HH;
    constexpr int NBLK = N / 128;
    __shared__ float Ws[32 * 129];
    __shared__ float Xs[64 * 33];
    int lb = blockIdx.x & 1;
    int tmp = blockIdx.x >> 1;
    int nb = tmp & (NBLK - 1);
    int b = tmp / NBLK;
    const float* W = (LAYER == 1) ? g_w1 : (LAYER == 2) ? g_w2 : (LAYER == 3) ? g_w3 : g_w4;
    const float* in = (LAYER == 1) ? extin : (LAYER == 2) ? g_ea : (LAYER == 3) ? g_eb : g_ea;
    const float* Wb = W + ((size_t)b * N + nb * 128) * K;
    const float* Ib = in + ((size_t)b * LL + lb * 64) * K;
    int tid = threadIdx.x;
    int tc = tid & 31, tr = tid >> 5;
    float acc[8][4];
#pragma unroll
    for (int i = 0; i < 8; i++)
#pragma unroll
        for (int d = 0; d < 4; d++) acc[i][d] = 0.f;
    for (int kc = 0; kc < K; kc += 32) {
#pragma unroll
        for (int s = 0; s < 16; s++) {
            int e = tid + s * 256;
            int kk = e & 31, n = e >> 5;
            Ws[kk * 129 + n] = Wb[(size_t)n * K + kc + kk];
        }
#pragma unroll
        for (int s = 0; s < 8; s++) {
            int e = tid + s * 256;
            int kk = e & 31, l = e >> 5;
            Xs[l * 33 + kk] = Ib[(size_t)l * K + kc + kk];
        }
        __syncthreads();
#pragma unroll
        for (int kk = 0; kk < 32; kk++) {
            float w0 = Ws[kk * 129 + tc];
            float w1 = Ws[kk * 129 + tc + 32];
            float w2 = Ws[kk * 129 + tc + 64];
            float w3 = Ws[kk * 129 + tc + 96];
#pragma unroll
            for (int i = 0; i < 8; i++) {
                float xv = Xs[(tr * 8 + i) * 33 + kk];
                acc[i][0] = fmaf(xv, w0, acc[i][0]);
                acc[i][1] = fmaf(xv, w1, acc[i][1]);
                acc[i][2] = fmaf(xv, w2, acc[i][2]);
                acc[i][3] = fmaf(xv, w3, acc[i][3]);
            }
        }
        __syncthreads();
    }
    float bv[4] = {0.f, 0.f, 0.f, 0.f};
    if (LAYER != 4) {
        const float* bias = (LAYER == 1) ? g_b1 : (LAYER == 2) ? g_b2 : g_b3;
#pragma unroll
        for (int d = 0; d < 4; d++) bv[d] = bias[b * HH + nb * 128 + tc + 32 * d];
    }
    float* op = (LAYER == 4) ? outp : (LAYER == 1) ? g_ea : (LAYER == 2) ? g_eb : g_ea;
#pragma unroll
    for (int i = 0; i < 8; i++) {
        int l = lb * 64 + tr * 8 + i;
        size_t rowo = ((size_t)b * LL + l) * N + nb * 128;
#pragma unroll
        for (int d = 0; d < 4; d++) {
            float v = acc[i][d];
            if (LAYER != 4) v = fmaxf(v + bv[d], 0.f);
            if (LAYER == 3) v *= gate[((size_t)b * LL + l) * HH + nb * 128 + tc + 32 * d];
            op[rowo + tc + 32 * d] = v;
        }
    }
}

// ---------------- final loss + scalar outputs ----------------------------------
__global__ void k_loss(const float* __restrict__ ty, const float* __restrict__ loglr,
                       float* __restrict__ out) {
    int gw = (blockIdx.x * blockDim.x + threadIdx.x) >> 5;
    int lane = threadIdx.x & 31;
    if (gw >= BB * LL) return;
    const float* lg = out + 4097 + (size_t)gw * YY;
    const float* tyv = ty + (size_t)gw * YY;
    float acc = 0.f;
#pragma unroll
    for (int k = lane, it = 0; it < YY / 32; it++, k += 32) {
        float d = lg[k] - tyv[k];
        acc = fmaf(d, d, acc);
    }
    acc = warp_sum(acc);
    if (lane == 0) {
        float m = acc * (1.f / (float)YY);
        out[gw] = m;
        out[2049 + gw] = m;
    }
    if (gw == 0 && lane == 0) out[2048] = expf(*loglr);
}

// ---------------- launch --------------------------------------------------------
extern "C" void kernel_launch(void* const* d_in, const int* in_sizes, int n_in,
                              void* d_out, int out_size) {
    const float* train_x = (const float*)d_in[0];
    const float* train_y = (const float*)d_in[1];
    const float* test_x = (const float*)d_in[2];
    const float* test_y = (const float*)d_in[3];
    const float* train_gate = (const float*)d_in[4];
    const float* test_gate = (const float*)d_in[5];
    const float* fc1 = (const float*)d_in[6];
    const float* b1 = (const float*)d_in[7];
    const float* fc2 = (const float*)d_in[8];
    const float* b2 = (const float*)d_in[9];
    const float* fc3 = (const float*)d_in[10];
    const float* b3 = (const float*)d_in[11];
    const float* fc4 = (const float*)d_in[12];
    const float* loglr = (const float*)d_in[13];
    float* out = (float*)d_out;

    k_tr<<<640, 256>>>(fc2, fc3, fc4);
    k_misc<<<64, 256>>>(b1, b2, b3, train_x);
    k_train<<<64, TPB>>>(train_x, train_y, train_gate, fc1, fc2, fc3, fc4, loglr);
    k_material<<<2048, 256>>>(fc1, fc2, fc3, fc4, train_x, loglr);

    k_eval<1><<<BB * (HH / 128) * 2, 256>>>(test_x, nullptr, nullptr);
    k_eval<2><<<BB * (HH / 128) * 2, 256>>>(nullptr, nullptr, nullptr);
    k_eval<3><<<BB * (HH / 128) * 2, 256>>>(nullptr, test_gate, nullptr);
    k_eval<4><<<BB * (YY / 128) * 2, 256>>>(nullptr, nullptr, out + 4097);

    k_loss<<<256, 256>>>(test_y, loglr, out);
}